// round 15
// baseline (speedup 1.0000x reference)
#include <cuda_runtime.h>
#include <math.h>
#include <stdint.h>

#define BATCH 2
#define SEQN 2048
#define SEQM 2048
#define DIM 1024
#define HEADS 16
#define DH 64
#define ATT_SCALE 0.125f
#define LN_EPS 1e-5f

// ---------------- scratch (static device memory; no allocation) ----------------
__device__ float g_xn[BATCH * SEQN * DIM];
__device__ float g_cn[BATCH * SEQM * DIM];
__device__ float g_q [BATCH * SEQN * DIM];
__device__ float g_k [BATCH * SEQM * DIM];
__device__ float g_v [BATCH * SEQM * DIM];
__device__ float g_ao[BATCH * SEQN * DIM];

// ---------------- helpers ----------------
__device__ __forceinline__ uint32_t f2tf(float f) {
    uint32_t r;
    asm("cvt.rna.tf32.f32 %0, %1;" : "=r"(r) : "f"(f));
    return r;
}

__device__ __forceinline__ void mma_tf32(float* c, const uint32_t* a, uint32_t b0, uint32_t b1) {
    asm volatile(
        "mma.sync.aligned.m16n8k8.row.col.f32.tf32.tf32.f32 "
        "{%0,%1,%2,%3}, {%4,%5,%6,%7}, {%8,%9}, {%0,%1,%2,%3};\n"
        : "+f"(c[0]), "+f"(c[1]), "+f"(c[2]), "+f"(c[3])
        : "r"(a[0]), "r"(a[1]), "r"(a[2]), "r"(a[3]), "r"(b0), "r"(b1));
}

// ---------------- LayerNorm: one block per row ----------------
__global__ __launch_bounds__(256) void ln_kernel(
    const float* __restrict__ x, const float* __restrict__ ctx,
    const float* __restrict__ w, const float* __restrict__ b,
    float* __restrict__ xn, float* __restrict__ cn)
{
    int row = blockIdx.x;
    const float* in;
    float* out;
    if (row < BATCH * SEQN) {
        in = x + (size_t)row * DIM;
        out = xn + (size_t)row * DIM;
    } else {
        int r = row - BATCH * SEQN;
        in = ctx + (size_t)r * DIM;
        out = cn + (size_t)r * DIM;
    }
    int tid = threadIdx.x;
    float4 v4 = ((const float4*)in)[tid];
    float s  = v4.x + v4.y + v4.z + v4.w;
    float s2 = v4.x*v4.x + v4.y*v4.y + v4.z*v4.z + v4.w*v4.w;

    #pragma unroll
    for (int off = 16; off > 0; off >>= 1) {
        s  += __shfl_xor_sync(0xffffffffu, s,  off);
        s2 += __shfl_xor_sync(0xffffffffu, s2, off);
    }
    __shared__ float rs[8], rs2[8];
    int wid = tid >> 5, lid = tid & 31;
    if (lid == 0) { rs[wid] = s; rs2[wid] = s2; }
    __syncthreads();
    if (wid == 0) {
        s  = (lid < 8) ? rs[lid]  : 0.f;
        s2 = (lid < 8) ? rs2[lid] : 0.f;
        #pragma unroll
        for (int off = 4; off > 0; off >>= 1) {
            s  += __shfl_xor_sync(0xffffffffu, s,  off);
            s2 += __shfl_xor_sync(0xffffffffu, s2, off);
        }
        if (lid == 0) { rs[0] = s; rs2[0] = s2; }
    }
    __syncthreads();
    float mu  = rs[0] * (1.0f / DIM);
    float var = rs2[0] * (1.0f / DIM) - mu * mu;
    float inv = rsqrtf(var + LN_EPS);

    float4 w4 = ((const float4*)w)[tid];
    float4 b4 = ((const float4*)b)[tid];
    float4 o4;
    o4.x = (v4.x - mu) * inv * w4.x + b4.x;
    o4.y = (v4.y - mu) * inv * w4.y + b4.y;
    o4.z = (v4.z - mu) * inv * w4.z + b4.z;
    o4.w = (v4.w - mu) * inv * w4.w + b4.w;
    ((float4*)out)[tid] = o4;
}

// ---------------- tf32 GEMM body: C[M,N] = A[M,K] @ W[N,K]^T (+bias) --------
// 128x128 tile, BK=32, 256 threads (8 warps, 2x4), warp tile 64x32.
// Single-buffer smem, LDG prefetch into regs, LDS.64 fragment loads via
// consistent k-permutation (mma k-slots 0/1 <- physical cols 2q/2q+1 on BOTH
// operands, so every dot product sums the same 8 k-terms).
#define SAS 40   // stride mod 32 == 8 -> conflict-free uint2 fragment loads

__device__ __forceinline__ void gemm_body(
    const float* __restrict__ A, const float* __restrict__ W,
    float* __restrict__ C, const float* __restrict__ bias,
    uint32_t* sA, uint32_t* sB, int m0, int n0)
{
    int tid = threadIdx.x;
    int lane = tid & 31, w = tid >> 5;
    int g = lane >> 2, q = lane & 3;
    int wm = (w >> 2) * 64, wn = (w & 3) * 32;

    int lr = tid >> 1;          // 0..127
    int lk = (tid & 1) * 16;    // 0 or 16

    const float* Ap = A + (size_t)(m0 + lr) * DIM + lk;
    const float* Wp = W + (size_t)(n0 + lr) * DIM + lk;

    float acc[4][4][4];
    #pragma unroll
    for (int mt = 0; mt < 4; mt++)
        #pragma unroll
        for (int nt = 0; nt < 4; nt++)
            #pragma unroll
            for (int i = 0; i < 4; i++) acc[mt][nt][i] = 0.f;

    for (int k0 = 0; k0 < DIM; k0 += 32) {
        float4 av[4], wv[4];
        #pragma unroll
        for (int i = 0; i < 4; i++) {
            av[i] = *(const float4*)(Ap + k0 + i * 4);
            wv[i] = *(const float4*)(Wp + k0 + i * 4);
        }
        __syncthreads();
        #pragma unroll
        for (int i = 0; i < 4; i++) {
            *(uint4*)&sA[lr * SAS + lk + i * 4] =
                make_uint4(f2tf(av[i].x), f2tf(av[i].y), f2tf(av[i].z), f2tf(av[i].w));
            *(uint4*)&sB[lr * SAS + lk + i * 4] =
                make_uint4(f2tf(wv[i].x), f2tf(wv[i].y), f2tf(wv[i].z), f2tf(wv[i].w));
        }
        __syncthreads();

        #pragma unroll
        for (int ks = 0; ks < 4; ks++) {
            int c = ks * 8 + 2 * q;
            uint32_t af[4][4], bf[4][2];
            #pragma unroll
            for (int mt = 0; mt < 4; mt++) {
                int r = wm + mt * 16 + g;
                uint2 t0 = *(const uint2*)&sA[r * SAS + c];
                uint2 t1 = *(const uint2*)&sA[(r + 8) * SAS + c];
                af[mt][0] = t0.x; af[mt][2] = t0.y;
                af[mt][1] = t1.x; af[mt][3] = t1.y;
            }
            #pragma unroll
            for (int nt = 0; nt < 4; nt++) {
                int rn = wn + nt * 8 + g;
                uint2 tb = *(const uint2*)&sB[rn * SAS + c];
                bf[nt][0] = tb.x; bf[nt][1] = tb.y;
            }
            #pragma unroll
            for (int mt = 0; mt < 4; mt++)
                #pragma unroll
                for (int nt = 0; nt < 4; nt++)
                    mma_tf32(acc[mt][nt], af[mt], bf[nt][0], bf[nt][1]);
        }
    }

    #pragma unroll
    for (int mt = 0; mt < 4; mt++) {
        #pragma unroll
        for (int nt = 0; nt < 4; nt++) {
            int row = m0 + wm + mt * 16 + g;
            int col = n0 + wn + nt * 8 + 2 * q;
            float b0 = bias ? bias[col] : 0.f;
            float b1 = bias ? bias[col + 1] : 0.f;
            float2 o0, o1;
            o0.x = acc[mt][nt][0] + b0; o0.y = acc[mt][nt][1] + b1;
            o1.x = acc[mt][nt][2] + b0; o1.y = acc[mt][nt][3] + b1;
            *(float2*)&C[(size_t)row * DIM + col] = o0;
            *(float2*)&C[(size_t)(row + 8) * DIM + col] = o1;
        }
    }
}

// Fused Q/K/V projections: blockIdx.z selects {Wq->q, Wk->k, Wv->v}.
__global__ __launch_bounds__(256) void gemm_qkv(
    const float* __restrict__ Wq, const float* __restrict__ Wk,
    const float* __restrict__ Wv)
{
    __shared__ uint32_t sA[128 * SAS];
    __shared__ uint32_t sB[128 * SAS];
    int z = blockIdx.z;
    const float* A = (z == 0) ? g_xn : g_cn;
    const float* W = (z == 0) ? Wq : (z == 1) ? Wk : Wv;
    float* C = (z == 0) ? g_q : (z == 1) ? g_k : g_v;
    gemm_body(A, W, C, nullptr, sA, sB, blockIdx.y * 128, blockIdx.x * 128);
}

// Output projection with bias.
__global__ __launch_bounds__(256) void gemm_out(
    const float* __restrict__ W, float* __restrict__ C,
    const float* __restrict__ bias)
{
    __shared__ uint32_t sA[128 * SAS];
    __shared__ uint32_t sB[128 * SAS];
    gemm_body(g_ao, W, C, bias, sA, sB, blockIdx.y * 128, blockIdx.x * 128);
}

// ---------------- tensor-core flash attention with alibi --------------------
// Block: 128 q-rows of one (b,h). 256 threads = 8 warps, warp owns 16 rows.
// KV tile = 64, single buffer. P passes S->PV directly in registers:
// C-frag of S (rows g/g+8, cols 2q/2q+1) == A-frag for PV (k-slots 2q/2q+1)
// because V's b-frag rows also use j = ks*8 + 2q/2q+1 (consistent k-perm).
#define KST 72   // stride mod 32 == 8: conflict-free for row-by-g indexed loads
#define VST 68   // stride mod 32 == 4: conflict-free for row-by-2q indexed loads

__global__ __launch_bounds__(256) void attn_tc(const float* __restrict__ alibi)
{
    extern __shared__ uint32_t dsm[];
    uint32_t* sK = dsm;                          // [64][KST]
    uint32_t* sV = dsm + 64 * KST;               // [64][VST]
    uint32_t* sQ = dsm + 64 * KST + 64 * VST;    // [128][KST] (Q staging only)

    int tid = threadIdx.x;
    int lane = tid & 31, w = tid >> 5;
    int g = lane >> 2, q = lane & 3;
    int bi = blockIdx.x, h = blockIdx.z, i0 = blockIdx.y * 128;

    // stage Q (scaled, tf32)
    {
        int r = tid >> 1;
        int cb = (tid & 1) * 32;
        const float* qp = g_q + ((size_t)(bi * SEQN + i0 + r)) * DIM + h * DH + cb;
        #pragma unroll
        for (int i = 0; i < 8; i++) {
            float4 t = *(const float4*)(qp + i * 4);
            *(uint4*)&sQ[r * KST + cb + i * 4] =
                make_uint4(f2tf(t.x * ATT_SCALE), f2tf(t.y * ATT_SCALE),
                           f2tf(t.z * ATT_SCALE), f2tf(t.w * ATT_SCALE));
        }
    }
    __syncthreads();

    uint32_t qf[8][4];
    #pragma unroll
    for (int ks = 0; ks < 8; ks++) {
        int r = w * 16 + g, c = ks * 8 + 2 * q;
        uint2 t0 = *(const uint2*)&sQ[r * KST + c];
        uint2 t1 = *(const uint2*)&sQ[(r + 8) * KST + c];
        qf[ks][0] = t0.x; qf[ks][2] = t0.y;
        qf[ks][1] = t1.x; qf[ks][3] = t1.y;
    }
    __syncthreads();

    float o[8][4];
    #pragma unroll
    for (int nt = 0; nt < 8; nt++)
        #pragma unroll
        for (int i = 0; i < 4; i++) o[nt][i] = 0.f;
    float m0r = -3.0e38f, m1r = -3.0e38f, l0 = 0.f, l1 = 0.f;

    const size_t alr0 = ((size_t)h * SEQN + (i0 + w * 16 + g)) * (size_t)SEQM + 2 * q;
    const size_t alr1 = alr0 + 8 * (size_t)SEQM;

    int kr = tid >> 2, kc = tid & 3;
    const float* kbase = g_k + ((size_t)(bi * SEQM + kr)) * DIM + h * DH;
    const float* vbase = g_v + ((size_t)(bi * SEQM + kr)) * DIM + h * DH;

    for (int j0 = 0; j0 < SEQM; j0 += 64) {
        float4 kv4[4], vv4[4];
        #pragma unroll
        for (int i = 0; i < 4; i++) {
            kv4[i] = *(const float4*)(kbase + (size_t)j0 * DIM + kc * 4 + i * 16);
            vv4[i] = *(const float4*)(vbase + (size_t)j0 * DIM + kc * 4 + i * 16);
        }
        __syncthreads();
        #pragma unroll
        for (int i = 0; i < 4; i++) {
            int c = kc * 4 + i * 16;
            *(uint4*)&sK[kr * KST + c] =
                make_uint4(f2tf(kv4[i].x), f2tf(kv4[i].y), f2tf(kv4[i].z), f2tf(kv4[i].w));
            *(uint4*)&sV[kr * VST + c] =
                make_uint4(f2tf(vv4[i].x), f2tf(vv4[i].y), f2tf(vv4[i].z), f2tf(vv4[i].w));
        }
        __syncthreads();

        // S = alibi + Q K^T (alibi LDGs hoisted ahead of mma chain)
        float s[8][4];
        #pragma unroll
        for (int nt = 0; nt < 8; nt++) {
            float2 a0 = *(const float2*)(alibi + alr0 + j0 + nt * 8);
            float2 a1 = *(const float2*)(alibi + alr1 + j0 + nt * 8);
            s[nt][0] = a0.x; s[nt][1] = a0.y; s[nt][2] = a1.x; s[nt][3] = a1.y;
        }
        #pragma unroll
        for (int nt = 0; nt < 8; nt++) {
            #pragma unroll
            for (int ks = 0; ks < 8; ks++) {
                uint2 tb = *(const uint2*)&sK[(nt * 8 + g) * KST + ks * 8 + 2 * q];
                mma_tf32(s[nt], qf[ks], tb.x, tb.y);
            }
        }

        // online softmax (rows g, g+8)
        float tm0 = -3.0e38f, tm1 = -3.0e38f;
        #pragma unroll
        for (int nt = 0; nt < 8; nt++) {
            tm0 = fmaxf(tm0, fmaxf(s[nt][0], s[nt][1]));
            tm1 = fmaxf(tm1, fmaxf(s[nt][2], s[nt][3]));
        }
        tm0 = fmaxf(tm0, __shfl_xor_sync(0xffffffffu, tm0, 1));
        tm0 = fmaxf(tm0, __shfl_xor_sync(0xffffffffu, tm0, 2));
        tm1 = fmaxf(tm1, __shfl_xor_sync(0xffffffffu, tm1, 1));
        tm1 = fmaxf(tm1, __shfl_xor_sync(0xffffffffu, tm1, 2));

        float mn0 = fmaxf(m0r, tm0), mn1 = fmaxf(m1r, tm1);
        float c0 = __expf(m0r - mn0), c1 = __expf(m1r - mn1);
        l0 *= c0; l1 *= c1;
        #pragma unroll
        for (int nt = 0; nt < 8; nt++) {
            o[nt][0] *= c0; o[nt][1] *= c0;
            o[nt][2] *= c1; o[nt][3] *= c1;
        }
        m0r = mn0; m1r = mn1;

        float ps0 = 0.f, ps1 = 0.f;
        #pragma unroll
        for (int nt = 0; nt < 8; nt++) {
            s[nt][0] = __expf(s[nt][0] - mn0);
            s[nt][1] = __expf(s[nt][1] - mn0);
            s[nt][2] = __expf(s[nt][2] - mn1);
            s[nt][3] = __expf(s[nt][3] - mn1);
            ps0 += s[nt][0] + s[nt][1]; ps1 += s[nt][2] + s[nt][3];
        }
        ps0 += __shfl_xor_sync(0xffffffffu, ps0, 1);
        ps0 += __shfl_xor_sync(0xffffffffu, ps0, 2);
        ps1 += __shfl_xor_sync(0xffffffffu, ps1, 1);
        ps1 += __shfl_xor_sync(0xffffffffu, ps1, 2);
        l0 += ps0; l1 += ps1;

        // O += P V, P fragments direct from S accumulators (no smem round-trip)
        #pragma unroll
        for (int ks = 0; ks < 8; ks++) {
            int c = ks * 8 + 2 * q;
            uint32_t af[4];
            af[0] = f2tf(s[ks][0]); af[1] = f2tf(s[ks][2]);
            af[2] = f2tf(s[ks][1]); af[3] = f2tf(s[ks][3]);
            #pragma unroll
            for (int nt = 0; nt < 8; nt++) {
                uint32_t b0 = sV[(c) * VST + nt * 8 + g];
                uint32_t b1 = sV[(c + 1) * VST + nt * 8 + g];
                mma_tf32(o[nt], af, b0, b1);
            }
        }
    }

    float inv0 = 1.f / l0, inv1 = 1.f / l1;
    size_t orow = (size_t)(bi * SEQN + i0 + w * 16 + g) * DIM + h * DH;
    #pragma unroll
    for (int nt = 0; nt < 8; nt++) {
        int col = nt * 8 + 2 * q;
        float2 t0, t1;
        t0.x = o[nt][0] * inv0; t0.y = o[nt][1] * inv0;
        t1.x = o[nt][2] * inv1; t1.y = o[nt][3] * inv1;
        *(float2*)&g_ao[orow + col] = t0;
        *(float2*)&g_ao[orow + 8 * DIM + col] = t1;
    }
}

// ---------------- launch ----------------
extern "C" void kernel_launch(void* const* d_in, const int* in_sizes, int n_in,
                              void* d_out, int out_size)
{
    const float* x     = (const float*)d_in[0];
    const float* ctx   = (const float*)d_in[1];
    const float* alibi = (const float*)d_in[2];
    const float* Wq    = (const float*)d_in[3];
    const float* Wk    = (const float*)d_in[4];
    const float* Wv    = (const float*)d_in[5];
    const float* Wo    = (const float*)d_in[6];
    const float* bo    = (const float*)d_in[7];
    const float* ln_w  = (const float*)d_in[8];
    const float* ln_b  = (const float*)d_in[9];
    float* out = (float*)d_out;

    float *p_xn, *p_cn;
    cudaGetSymbolAddress((void**)&p_xn, g_xn);
    cudaGetSymbolAddress((void**)&p_cn, g_cn);

    const int attn_smem = (64 * KST + 64 * VST + 128 * KST) * 4;
    cudaFuncSetAttribute(attn_tc, cudaFuncAttributeMaxDynamicSharedMemorySize, attn_smem);

    // LayerNorm x and context
    ln_kernel<<<BATCH * SEQN + BATCH * SEQM, 256>>>(x, ctx, ln_w, ln_b, p_xn, p_cn);

    // Fused Q/K/V projections (one launch, 768 CTAs)
    dim3 qkvgrid(DIM / 128, (BATCH * SEQN) / 128, 3);
    gemm_qkv<<<qkvgrid, 256>>>(Wq, Wk, Wv);

    // Flash attention with alibi; batch fastest so b=0/b=1 share alibi via L2
    dim3 agrid(BATCH, SEQN / 128, HEADS);
    attn_tc<<<agrid, 256, attn_smem>>>(alibi);

    // Output projection + bias -> d_out
    dim3 ogrid(DIM / 128, (BATCH * SEQN) / 128);
    gemm_out<<<ogrid, 256>>>(Wo, out, bo);
}

// round 17
// speedup vs baseline: 1.3627x; 1.3627x over previous
#include <cuda_runtime.h>
#include <cuda_fp16.h>
#include <math.h>
#include <stdint.h>

#define BATCH 2
#define SEQN 2048
#define SEQM 2048
#define DIM 1024
#define HEADS 16
#define DH 64
#define ATT_SCALE 0.125f
#define LN_EPS 1e-5f

// ---------------- scratch (static device memory; no allocation) ----------------
__device__ float g_xn[BATCH * SEQN * DIM];
__device__ float g_cn[BATCH * SEQM * DIM];
__device__ float g_q [BATCH * SEQN * DIM];
__device__ float g_k [BATCH * SEQM * DIM];
__device__ float g_v [BATCH * SEQM * DIM];
__device__ float g_ao[BATCH * SEQN * DIM];

// ---------------- helpers ----------------
// pack two floats into half2 (lo, hi), round-to-nearest
__device__ __forceinline__ uint32_t h2pk(float lo, float hi) {
    uint32_t r;
    asm("cvt.rn.f16x2.f32 %0, %1, %2;" : "=r"(r) : "f"(hi), "f"(lo));
    return r;
}

// m16n8k16 fp16 mma, fp32 accumulate
__device__ __forceinline__ void mma_f16(float* c, const uint32_t* a, uint32_t b0, uint32_t b1) {
    asm volatile(
        "mma.sync.aligned.m16n8k16.row.col.f32.f16.f16.f32 "
        "{%0,%1,%2,%3}, {%4,%5,%6,%7}, {%8,%9}, {%0,%1,%2,%3};\n"
        : "+f"(c[0]), "+f"(c[1]), "+f"(c[2]), "+f"(c[3])
        : "r"(a[0]), "r"(a[1]), "r"(a[2]), "r"(a[3]), "r"(b0), "r"(b1));
}

// Pack 16 consecutive-k floats (f0..f15 as 4 float4) into the slot-permuted
// physical order [k0,k1,k8,k9, k2,k3,k10,k11, k4,k5,k12,k13, k6,k7,k14,k15]
// so that one LDS.64 at byte 8q yields {pair(2q), pair(2q+1)} =
// {a-slots 2q,2q+1} and {a-slots 8+2q,8+2q+1}.
__device__ __forceinline__ void pack16(const float4& A, const float4& B,
                                       const float4& C, const float4& D,
                                       uint4& lo, uint4& hi) {
    // f0..3 = A, f4..7 = B, f8..11 = C, f12..15 = D
    lo.x = h2pk(A.x, A.y);  lo.y = h2pk(C.x, C.y);
    lo.z = h2pk(A.z, A.w);  lo.w = h2pk(C.z, C.w);
    hi.x = h2pk(B.x, B.y);  hi.y = h2pk(D.x, D.y);
    hi.z = h2pk(B.z, B.w);  hi.w = h2pk(D.z, D.w);
}

// ---------------- LayerNorm: one block per row ----------------
__global__ __launch_bounds__(256) void ln_kernel(
    const float* __restrict__ x, const float* __restrict__ ctx,
    const float* __restrict__ w, const float* __restrict__ b,
    float* __restrict__ xn, float* __restrict__ cn)
{
    int row = blockIdx.x;
    const float* in;
    float* out;
    if (row < BATCH * SEQN) {
        in = x + (size_t)row * DIM;
        out = xn + (size_t)row * DIM;
    } else {
        int r = row - BATCH * SEQN;
        in = ctx + (size_t)r * DIM;
        out = cn + (size_t)r * DIM;
    }
    int tid = threadIdx.x;
    float4 v4 = ((const float4*)in)[tid];
    float s  = v4.x + v4.y + v4.z + v4.w;
    float s2 = v4.x*v4.x + v4.y*v4.y + v4.z*v4.z + v4.w*v4.w;

    #pragma unroll
    for (int off = 16; off > 0; off >>= 1) {
        s  += __shfl_xor_sync(0xffffffffu, s,  off);
        s2 += __shfl_xor_sync(0xffffffffu, s2, off);
    }
    __shared__ float rs[8], rs2[8];
    int wid = tid >> 5, lid = tid & 31;
    if (lid == 0) { rs[wid] = s; rs2[wid] = s2; }
    __syncthreads();
    if (wid == 0) {
        s  = (lid < 8) ? rs[lid]  : 0.f;
        s2 = (lid < 8) ? rs2[lid] : 0.f;
        #pragma unroll
        for (int off = 4; off > 0; off >>= 1) {
            s  += __shfl_xor_sync(0xffffffffu, s,  off);
            s2 += __shfl_xor_sync(0xffffffffu, s2, off);
        }
        if (lid == 0) { rs[0] = s; rs2[0] = s2; }
    }
    __syncthreads();
    float mu  = rs[0] * (1.0f / DIM);
    float var = rs2[0] * (1.0f / DIM) - mu * mu;
    float inv = rsqrtf(var + LN_EPS);

    float4 w4 = ((const float4*)w)[tid];
    float4 b4 = ((const float4*)b)[tid];
    float4 o4;
    o4.x = (v4.x - mu) * inv * w4.x + b4.x;
    o4.y = (v4.y - mu) * inv * w4.y + b4.y;
    o4.z = (v4.z - mu) * inv * w4.z + b4.z;
    o4.w = (v4.w - mu) * inv * w4.w + b4.w;
    ((float4*)out)[tid] = o4;
}

// ---------------- fp16 GEMM body: C[M,N] = A[M,K] @ W[N,K]^T (+bias) --------
// 128x128 tile, BK=32, 256 threads (8 warps, 2x4), warp tile 64x32.
// fp16 m16n8k16 mma, slot-permuted smem rows (32 halves + pad, stride 96B),
// 16B XOR swizzle by row parity: staging STS.128 and fragment LDS.64 are
// both bank-conflict-free (verified per 8/16-lane phase).
#define GST 96   // smem row stride in bytes (64B data + 32B pad; 24w % 32 = 24)

__device__ __forceinline__ void gemm_body(
    const float* __restrict__ A, const float* __restrict__ W,
    float* __restrict__ C, const float* __restrict__ bias,
    char* sA, char* sB, int m0, int n0)
{
    int tid = threadIdx.x;
    int lane = tid & 31, w = tid >> 5;
    int g = lane >> 2, q = lane & 3;
    int wm = (w >> 2) * 64, wn = (w & 3) * 32;

    int lr = tid >> 1;          // 0..127 row
    int grp = tid & 1;          // k16 group within BK=32

    const float* Ap = A + (size_t)(m0 + lr) * DIM + grp * 16;
    const float* Wp = W + (size_t)(n0 + lr) * DIM + grp * 16;
    int sbase = lr * GST + grp * 32;
    int sx = (lr & 1) * 16;

    float acc[4][4][4];
    #pragma unroll
    for (int mt = 0; mt < 4; mt++)
        #pragma unroll
        for (int nt = 0; nt < 4; nt++)
            #pragma unroll
            for (int i = 0; i < 4; i++) acc[mt][nt][i] = 0.f;

    for (int k0 = 0; k0 < DIM; k0 += 32) {
        float4 a4[4], w4[4];
        #pragma unroll
        for (int i = 0; i < 4; i++) {
            a4[i] = *(const float4*)(Ap + k0 + i * 4);
            w4[i] = *(const float4*)(Wp + k0 + i * 4);
        }
        __syncthreads();
        {
            uint4 lo, hi;
            pack16(a4[0], a4[1], a4[2], a4[3], lo, hi);
            *(uint4*)(sA + sbase + (0 ^ sx))  = lo;
            *(uint4*)(sA + sbase + (16 ^ sx)) = hi;
            pack16(w4[0], w4[1], w4[2], w4[3], lo, hi);
            *(uint4*)(sB + sbase + (0 ^ sx))  = lo;
            *(uint4*)(sB + sbase + (16 ^ sx)) = hi;
        }
        __syncthreads();

        #pragma unroll
        for (int ks = 0; ks < 2; ks++) {
            int xoff = (ks * 32 + 8 * q) ^ ((g & 1) * 16);
            uint32_t af[4][4], bf[4][2];
            #pragma unroll
            for (int mt = 0; mt < 4; mt++) {
                int r = wm + mt * 16 + g;
                uint2 t0 = *(const uint2*)(sA + r * GST + xoff);
                uint2 t1 = *(const uint2*)(sA + (r + 8) * GST + xoff);
                af[mt][0] = t0.x; af[mt][1] = t1.x;
                af[mt][2] = t0.y; af[mt][3] = t1.y;
            }
            #pragma unroll
            for (int nt = 0; nt < 4; nt++) {
                int rn = wn + nt * 8 + g;
                uint2 tb = *(const uint2*)(sB + rn * GST + xoff);
                bf[nt][0] = tb.x; bf[nt][1] = tb.y;
            }
            #pragma unroll
            for (int mt = 0; mt < 4; mt++)
                #pragma unroll
                for (int nt = 0; nt < 4; nt++)
                    mma_f16(acc[mt][nt], af[mt], bf[nt][0], bf[nt][1]);
        }
    }

    #pragma unroll
    for (int mt = 0; mt < 4; mt++) {
        #pragma unroll
        for (int nt = 0; nt < 4; nt++) {
            int row = m0 + wm + mt * 16 + g;
            int col = n0 + wn + nt * 8 + 2 * q;
            float b0 = bias ? bias[col] : 0.f;
            float b1 = bias ? bias[col + 1] : 0.f;
            float2 o0, o1;
            o0.x = acc[mt][nt][0] + b0; o0.y = acc[mt][nt][1] + b1;
            o1.x = acc[mt][nt][2] + b0; o1.y = acc[mt][nt][3] + b1;
            *(float2*)&C[(size_t)row * DIM + col] = o0;
            *(float2*)&C[(size_t)(row + 8) * DIM + col] = o1;
        }
    }
}

__global__ __launch_bounds__(256) void gemm_qkv(
    const float* __restrict__ Wq, const float* __restrict__ Wk,
    const float* __restrict__ Wv)
{
    __shared__ __align__(16) char sA[128 * GST];
    __shared__ __align__(16) char sB[128 * GST];
    int z = blockIdx.z;
    const float* A = (z == 0) ? g_xn : g_cn;
    const float* W = (z == 0) ? Wq : (z == 1) ? Wk : Wv;
    float* C = (z == 0) ? g_q : (z == 1) ? g_k : g_v;
    gemm_body(A, W, C, nullptr, sA, sB, blockIdx.y * 128, blockIdx.x * 128);
}

__global__ __launch_bounds__(256) void gemm_out(
    const float* __restrict__ W, float* __restrict__ C,
    const float* __restrict__ bias)
{
    __shared__ __align__(16) char sA[128 * GST];
    __shared__ __align__(16) char sB[128 * GST];
    gemm_body(g_ao, W, C, bias, sA, sB, blockIdx.y * 128, blockIdx.x * 128);
}

// ---------------- fp16 tensor-core flash attention with alibi ---------------
// Block: 128 q-rows of one (b,h). 256 threads = 8 warps, warp owns 16 rows.
// KV tile = 64. Q/K rows: 64 halves slot-permuted, stride 160B, 16B xor.
// V: pair-interleaved rows (half2 {V[2m][n],V[2m+1][n]}), 32 rows x 64 half2,
// stride 272B. P written half2 into sPQ (stride 160B) in permuted slot order.
#define QST 160   // Q/K/P row stride bytes (40w % 32 = 8 -> conflict-free)
#define VST2 272  // V pair-row stride bytes (68w % 32 = 4 -> conflict-free)

__global__ __launch_bounds__(256) void attn_tc(const float* __restrict__ alibi)
{
    __shared__ __align__(16) char sK [64 * QST];    // 10240 B
    __shared__ __align__(16) char sV [32 * VST2];   //  8704 B
    __shared__ __align__(16) char sPQ[128 * QST];   // 20480 B (Q, then P)

    int tid = threadIdx.x;
    int lane = tid & 31, w = tid >> 5;
    int g = lane >> 2, q = lane & 3;
    int bi = blockIdx.x, h = blockIdx.z, i0 = blockIdx.y * 128;

    // ---- stage Q (scaled, fp16, slot-permuted) ----
    {
        int r = tid >> 1;
        int gb = (tid & 1) * 2;   // group base (0 or 2), each group = 16 k
        const float* qp = g_q + ((size_t)(bi * SEQN + i0 + r)) * DIM + h * DH + (tid & 1) * 32;
        int x = (r & 1) * 16;
        #pragma unroll
        for (int gi = 0; gi < 2; gi++) {
            float4 f[4];
            #pragma unroll
            for (int i = 0; i < 4; i++) {
                float4 t = *(const float4*)(qp + gi * 16 + i * 4);
                f[i].x = t.x * ATT_SCALE; f[i].y = t.y * ATT_SCALE;
                f[i].z = t.z * ATT_SCALE; f[i].w = t.w * ATT_SCALE;
            }
            uint4 lo, hi;
            pack16(f[0], f[1], f[2], f[3], lo, hi);
            char* base = sPQ + r * QST + (gb + gi) * 32;
            *(uint4*)(base + (0 ^ x))  = lo;
            *(uint4*)(base + (16 ^ x)) = hi;
        }
    }
    __syncthreads();

    uint32_t qf[4][4];
    #pragma unroll
    for (int ks = 0; ks < 4; ks++) {
        int r = w * 16 + g;
        int xoff = (ks * 32 + 8 * q) ^ ((g & 1) * 16);
        uint2 t0 = *(const uint2*)(sPQ + r * QST + xoff);
        uint2 t1 = *(const uint2*)(sPQ + (r + 8) * QST + xoff);
        qf[ks][0] = t0.x; qf[ks][1] = t1.x;
        qf[ks][2] = t0.y; qf[ks][3] = t1.y;
    }
    __syncthreads();   // Q consumed; sPQ now reusable for P

    float o[8][4];
    #pragma unroll
    for (int nt = 0; nt < 8; nt++)
        #pragma unroll
        for (int i = 0; i < 4; i++) o[nt][i] = 0.f;
    float m0r = -3.0e38f, m1r = -3.0e38f, l0 = 0.f, l1 = 0.f;

    const size_t alr0 = ((size_t)h * SEQN + (i0 + w * 16 + g)) * (size_t)SEQM + 2 * q;
    const size_t alr1 = alr0 + 8 * (size_t)SEQM;

    // K staging indices: 4 threads per row, one k16 group each
    int kr = tid >> 2, kc = tid & 3;
    const float* kbase = g_k + ((size_t)(bi * SEQM + kr)) * DIM + h * DH + kc * 16;
    // V staging indices: pair-rows
    int vpr = tid & 31;                 // orig pair index m (rows 2m, 2m+1)
    int vcb = tid >> 5;                 // col-unit base (0..7)
    int vrow = ((vpr >> 3) << 3) | ((vpr & 3) << 1) | ((vpr >> 2) & 1);  // permuted pair-row
    const float* vbase0 = g_v + ((size_t)(bi * SEQM + 2 * vpr)) * DIM + h * DH;
    const float* vbase1 = vbase0 + DIM;

    for (int j0 = 0; j0 < SEQM; j0 += 64) {
        // prefetch K (4 float4) and V (2x2 float4) into regs
        float4 k4[4];
        #pragma unroll
        for (int i = 0; i < 4; i++)
            k4[i] = *(const float4*)(kbase + (size_t)j0 * DIM + i * 4);
        float4 v0[2], v1[2];
        #pragma unroll
        for (int it = 0; it < 2; it++) {
            int n0c = (vcb + it * 8) * 4;
            v0[it] = *(const float4*)(vbase0 + (size_t)j0 * DIM + n0c);
            v1[it] = *(const float4*)(vbase1 + (size_t)j0 * DIM + n0c);
        }
        __syncthreads();
        {
            uint4 lo, hi;
            pack16(k4[0], k4[1], k4[2], k4[3], lo, hi);
            int x = (kr & 1) * 16;
            char* base = sK + kr * QST + kc * 32;
            *(uint4*)(base + (0 ^ x))  = lo;
            *(uint4*)(base + (16 ^ x)) = hi;
            #pragma unroll
            for (int it = 0; it < 2; it++) {
                int n0c = (vcb + it * 8) * 4;
                uint4 u;
                u.x = h2pk(v0[it].x, v1[it].x);
                u.y = h2pk(v0[it].y, v1[it].y);
                u.z = h2pk(v0[it].z, v1[it].z);
                u.w = h2pk(v0[it].w, v1[it].w);
                *(uint4*)(sV + vrow * VST2 + n0c * 4) = u;
            }
        }
        __syncthreads();

        // S = alibi + Q K^T
        float s[8][4];
        #pragma unroll
        for (int nt = 0; nt < 8; nt++) {
            float2 a0 = *(const float2*)(alibi + alr0 + j0 + nt * 8);
            float2 a1 = *(const float2*)(alibi + alr1 + j0 + nt * 8);
            s[nt][0] = a0.x; s[nt][1] = a0.y; s[nt][2] = a1.x; s[nt][3] = a1.y;
        }
        #pragma unroll
        for (int nt = 0; nt < 8; nt++) {
            #pragma unroll
            for (int ks = 0; ks < 4; ks++) {
                int xoff = (ks * 32 + 8 * q) ^ ((g & 1) * 16);
                uint2 tb = *(const uint2*)(sK + (nt * 8 + g) * QST + xoff);
                mma_f16(s[nt], qf[ks], tb.x, tb.y);
            }
        }

        // online softmax (rows g, g+8)
        float tm0 = -3.0e38f, tm1 = -3.0e38f;
        #pragma unroll
        for (int nt = 0; nt < 8; nt++) {
            tm0 = fmaxf(tm0, fmaxf(s[nt][0], s[nt][1]));
            tm1 = fmaxf(tm1, fmaxf(s[nt][2], s[nt][3]));
        }
        tm0 = fmaxf(tm0, __shfl_xor_sync(0xffffffffu, tm0, 1));
        tm0 = fmaxf(tm0, __shfl_xor_sync(0xffffffffu, tm0, 2));
        tm1 = fmaxf(tm1, __shfl_xor_sync(0xffffffffu, tm1, 1));
        tm1 = fmaxf(tm1, __shfl_xor_sync(0xffffffffu, tm1, 2));

        float mn0 = fmaxf(m0r, tm0), mn1 = fmaxf(m1r, tm1);
        float c0 = __expf(m0r - mn0), c1 = __expf(m1r - mn1);
        l0 *= c0; l1 *= c1;
        #pragma unroll
        for (int nt = 0; nt < 8; nt++) {
            o[nt][0] *= c0; o[nt][1] *= c0;
            o[nt][2] *= c1; o[nt][3] *= c1;
        }
        m0r = mn0; m1r = mn1;

        float ps0 = 0.f, ps1 = 0.f;
        int prow = w * 16 + g;
        #pragma unroll
        for (int nt = 0; nt < 8; nt++) {
            float p0 = __expf(s[nt][0] - mn0);
            float p1 = __expf(s[nt][1] - mn0);
            float p2 = __expf(s[nt][2] - mn1);
            float p3 = __expf(s[nt][3] - mn1);
            ps0 += p0 + p1; ps1 += p2 + p3;
            // slot-permuted P write: group nt>>1, pair position 2q + (nt&1)
            int off = (nt >> 1) * 32 + (2 * q + (nt & 1)) * 4;
            *(uint32_t*)(sPQ + prow * QST + off)       = h2pk(p0, p1);
            *(uint32_t*)(sPQ + (prow + 8) * QST + off) = h2pk(p2, p3);
        }
        ps0 += __shfl_xor_sync(0xffffffffu, ps0, 1);
        ps0 += __shfl_xor_sync(0xffffffffu, ps0, 2);
        ps1 += __shfl_xor_sync(0xffffffffu, ps1, 1);
        ps1 += __shfl_xor_sync(0xffffffffu, ps1, 2);
        l0 += ps0; l1 += ps1;

        __syncwarp();   // P rows for this warp written/read only by this warp

        // O += P V
        #pragma unroll
        for (int ks = 0; ks < 4; ks++) {
            int off = ks * 32 + 8 * q;
            uint2 t0 = *(const uint2*)(sPQ + prow * QST + off);
            uint2 t1 = *(const uint2*)(sPQ + (prow + 8) * QST + off);
            uint32_t pa[4];
            pa[0] = t0.x; pa[1] = t1.x; pa[2] = t0.y; pa[3] = t1.y;
            #pragma unroll
            for (int nt = 0; nt < 8; nt++) {
                int col4 = (nt * 8 + g) * 4;
                uint32_t b0 = *(const uint32_t*)(sV + (ks * 8 + 2 * q) * VST2 + col4);
                uint32_t b1 = *(const uint32_t*)(sV + (ks * 8 + 2 * q + 1) * VST2 + col4);
                mma_f16(o[nt], pa, b0, b1);
            }
        }
    }

    float inv0 = 1.f / l0, inv1 = 1.f / l1;
    size_t orow = (size_t)(bi * SEQN + i0 + w * 16 + g) * DIM + h * DH;
    #pragma unroll
    for (int nt = 0; nt < 8; nt++) {
        int col = nt * 8 + 2 * q;
        float2 t0, t1;
        t0.x = o[nt][0] * inv0; t0.y = o[nt][1] * inv0;
        t1.x = o[nt][2] * inv1; t1.y = o[nt][3] * inv1;
        *(float2*)&g_ao[orow + col] = t0;
        *(float2*)&g_ao[orow + 8 * DIM + col] = t1;
    }
}

// ---------------- launch ----------------
extern "C" void kernel_launch(void* const* d_in, const int* in_sizes, int n_in,
                              void* d_out, int out_size)
{
    const float* x     = (const float*)d_in[0];
    const float* ctx   = (const float*)d_in[1];
    const float* alibi = (const float*)d_in[2];
    const float* Wq    = (const float*)d_in[3];
    const float* Wk    = (const float*)d_in[4];
    const float* Wv    = (const float*)d_in[5];
    const float* Wo    = (const float*)d_in[6];
    const float* bo    = (const float*)d_in[7];
    const float* ln_w  = (const float*)d_in[8];
    const float* ln_b  = (const float*)d_in[9];
    float* out = (float*)d_out;

    float *p_xn, *p_cn;
    cudaGetSymbolAddress((void**)&p_xn, g_xn);
    cudaGetSymbolAddress((void**)&p_cn, g_cn);

    // LayerNorm x and context
    ln_kernel<<<BATCH * SEQN + BATCH * SEQM, 256>>>(x, ctx, ln_w, ln_b, p_xn, p_cn);

    // Fused Q/K/V projections (one launch, 768 CTAs), fp16 tensor cores
    dim3 qkvgrid(DIM / 128, (BATCH * SEQN) / 128, 3);
    gemm_qkv<<<qkvgrid, 256>>>(Wq, Wk, Wv);

    // Flash attention with alibi; batch fastest so b=0/b=1 share alibi via L2
    dim3 agrid(BATCH, SEQN / 128, HEADS);
    attn_tc<<<agrid, 256>>>(alibi);

    // Output projection + bias -> d_out
    dim3 ogrid(DIM / 128, (BATCH * SEQN) / 128);
    gemm_out<<<ogrid, 256>>>(Wo, out, bo);
}